// round 15
// baseline (speedup 1.0000x reference)
#include <cuda_runtime.h>
#include <math.h>

#define UNITS 1024
#define FEAT  1024
#define GCOLS 4096                  // 4 * UNITS gate columns
#define GC4   (GCOLS / 4)           // 1024 float4 columns
#define NCB   4                     // column tiles (1024 scalar cols each)
#define C4T   256                   // float4 cols per block
#define KS    37                    // k-slices  -> grid 4 x 37 = 148 blocks
#define KR    28                    // k-rows per slice (37*28 = 1036 >= 1024)
#define KTG   4                     // kt groups (1024 threads / 256 cols)
#define KPT   7                     // k-rows per thread (28 / 4)

// Scratch (device globals)
__device__ float4 g_p0[KS][GC4];    // partials of x0@W (per k-slice)
__device__ float4 g_p1[KS][GC4];    // partials of x1@W
__device__ float4 g_pu[KS][GC4];    // partials of h0@U

__device__ __forceinline__ float sigmoidf_(float x) {
    return 1.0f / (1.0f + expf(-x));
}

// Fold the KS partials of a scalar gate column (fixed order) — deterministic.
__device__ __forceinline__ float fold_p(const float4 (*p)[GC4], int col) {
    const float* base = reinterpret_cast<const float*>(p);
    float s = 0.f;
    #pragma unroll
    for (int sI = 0; sI < KS; ++sI) s += base[sI * GCOLS + col];
    return s;
}

// ---------------------------------------------------------------------------
// Kernel 1: partial GEMV over W for t=0 and t=1.
// grid = (NCB, KS) = (4, 37) = 148 blocks x 1024 threads (one per SM).
// Block (cb, ks): scalar cols [cb*1024, +1024), k-rows [ks*28, +28) (guarded).
// Thread (c4 = tid&255, kt = tid>>8) covers rows kt + 4*kk, kk<7.
// A warp (32 consecutive c4, same kt) loads 512B contiguous per row.
// ---------------------------------------------------------------------------
__global__ void __launch_bounds__(1024, 1)
k_xw(const float* __restrict__ x, const float* __restrict__ W) {
    __shared__ float  xs0[KR], xs1[KR];
    __shared__ float4 sred0[KTG][C4T];
    __shared__ float4 sred1[KTG][C4T];
    const int tid = threadIdx.x;
    const int c4  = tid & (C4T - 1);
    const int kt  = tid >> 8;
    const int cb  = blockIdx.x;
    const int ks  = blockIdx.y;
    const int kbase = ks * KR;

    if (tid < KR) {
        const int k = kbase + tid;
        const bool v = (k < FEAT);
        xs0[tid] = v ? x[k] : 0.f;
        xs1[tid] = v ? x[FEAT + k] : 0.f;
    }
    __syncthreads();

    const float4* Wp = reinterpret_cast<const float4*>(W)
                     + (size_t)kbase * GC4 + cb * C4T + c4;
    float4 a0 = make_float4(0.f, 0.f, 0.f, 0.f);
    float4 a1 = make_float4(0.f, 0.f, 0.f, 0.f);
    #pragma unroll
    for (int kk = 0; kk < KPT; ++kk) {
        const int row = kt + KTG * kk;            // 0..27
        if (kbase + row < FEAT) {
            const float4 w = Wp[(size_t)row * GC4];
            const float xa = xs0[row];
            const float xb = xs1[row];
            a0.x = fmaf(xa, w.x, a0.x); a0.y = fmaf(xa, w.y, a0.y);
            a0.z = fmaf(xa, w.z, a0.z); a0.w = fmaf(xa, w.w, a0.w);
            a1.x = fmaf(xb, w.x, a1.x); a1.y = fmaf(xb, w.y, a1.y);
            a1.z = fmaf(xb, w.z, a1.z); a1.w = fmaf(xb, w.w, a1.w);
        }
    }
    sred0[kt][c4] = a0;
    sred1[kt][c4] = a1;
    __syncthreads();

    if (tid < C4T) {
        float4 s0 = make_float4(0.f, 0.f, 0.f, 0.f);
        float4 s1 = make_float4(0.f, 0.f, 0.f, 0.f);
        #pragma unroll
        for (int j = 0; j < KTG; ++j) {
            const float4 v0 = sred0[j][tid];
            const float4 v1 = sred1[j][tid];
            s0.x += v0.x; s0.y += v0.y; s0.z += v0.z; s0.w += v0.w;
            s1.x += v1.x; s1.y += v1.y; s1.z += v1.z; s1.w += v1.w;
        }
        g_p0[ks][cb * C4T + tid] = s0;
        g_p1[ks][cb * C4T + tid] = s1;
    }
}

// ---------------------------------------------------------------------------
// Kernel 2: partial GEMV over U. Same tiling; each block reconstructs the
// (up to) 28 h0 values it needs from the x@W partials (+b) first.
// c_prev = 0: c0 = sig(zi)*zg, h0 = sig(zo)*c0.
// ---------------------------------------------------------------------------
__global__ void __launch_bounds__(1024, 1)
k_hu(const float* __restrict__ U, const float* __restrict__ b) {
    __shared__ float  h0s[KR];
    __shared__ float4 sred[KTG][C4T];
    const int tid = threadIdx.x;
    const int c4  = tid & (C4T - 1);
    const int kt  = tid >> 8;
    const int cb  = blockIdx.x;
    const int ks  = blockIdx.y;
    const int kbase = ks * KR;

    if (tid < KR) {
        const int u = kbase + tid;
        if (u < FEAT) {
            const float zi = fold_p(g_p0, u)             + __ldg(b + u);
            const float zg = fold_p(g_p0, 2 * UNITS + u) + __ldg(b + 2 * UNITS + u);
            const float zo = fold_p(g_p0, 3 * UNITS + u) + __ldg(b + 3 * UNITS + u);
            const float c0 = sigmoidf_(zi) * zg;
            h0s[tid] = sigmoidf_(zo) * c0;
        } else {
            h0s[tid] = 0.f;
        }
    }
    __syncthreads();

    const float4* Up = reinterpret_cast<const float4*>(U)
                     + (size_t)kbase * GC4 + cb * C4T + c4;
    float4 a = make_float4(0.f, 0.f, 0.f, 0.f);
    #pragma unroll
    for (int kk = 0; kk < KPT; ++kk) {
        const int row = kt + KTG * kk;
        if (kbase + row < FEAT) {
            const float4 w = Up[(size_t)row * GC4];
            const float h = h0s[row];
            a.x = fmaf(h, w.x, a.x); a.y = fmaf(h, w.y, a.y);
            a.z = fmaf(h, w.z, a.z); a.w = fmaf(h, w.w, a.w);
        }
    }
    sred[kt][c4] = a;
    __syncthreads();

    if (tid < C4T) {
        float4 s = make_float4(0.f, 0.f, 0.f, 0.f);
        #pragma unroll
        for (int j = 0; j < KTG; ++j) {
            const float4 v = sred[j][tid];
            s.x += v.x; s.y += v.y; s.z += v.z; s.w += v.w;
        }
        g_pu[ks][cb * C4T + tid] = s;
    }
}

// ---------------------------------------------------------------------------
// Kernel 3: one block, 1024 threads = UNITS. Fold partials, gate math t0/t1,
// dense head via deterministic in-block reduction, finite diff, 4 outputs.
// ---------------------------------------------------------------------------
__global__ void k_final(const float* __restrict__ f,
                        const float* __restrict__ b,
                        const float* __restrict__ Wd,
                        const float* __restrict__ bd,
                        float* __restrict__ out) {
    __shared__ float red[4][32];
    const int u = threadIdx.x;

    const float zi0 = fold_p(g_p0, u)             + __ldg(b + u);
    const float zg0 = fold_p(g_p0, 2 * UNITS + u) + __ldg(b + 2 * UNITS + u);
    const float zo0 = fold_p(g_p0, 3 * UNITS + u) + __ldg(b + 3 * UNITS + u);
    const float c0  = sigmoidf_(zi0) * zg0;
    const float h0  = sigmoidf_(zo0) * c0;

    const float zi1 = fold_p(g_p1, u)             + fold_p(g_pu, u)             + __ldg(b + u);
    const float zf1 = fold_p(g_p1, UNITS + u)     + fold_p(g_pu, UNITS + u)     + __ldg(b + UNITS + u);
    const float zg1 = fold_p(g_p1, 2 * UNITS + u) + fold_p(g_pu, 2 * UNITS + u) + __ldg(b + 2 * UNITS + u);
    const float zo1 = fold_p(g_p1, 3 * UNITS + u) + fold_p(g_pu, 3 * UNITS + u) + __ldg(b + 3 * UNITS + u);
    const float c1  = sigmoidf_(zf1) * c0 + sigmoidf_(zi1) * zg1;
    const float h1  = sigmoidf_(zo1) * c1;

    const float n0 = tanhf(h0);
    const float n1 = tanhf(h1);

    const float wd0 = __ldg(Wd + 2 * u);
    const float wd1 = __ldg(Wd + 2 * u + 1);
    float v0 = n0 * wd0;   // -> h_c[0,0]
    float v1 = n0 * wd1;   // -> h_c[0,1]
    float v2 = n1 * wd0;   // -> h_c[1,0]
    float v3 = n1 * wd1;   // -> h_c[1,1]

    const unsigned m = 0xffffffffu;
    const int lane = u & 31;
    const int wrp  = u >> 5;
    #pragma unroll
    for (int off = 16; off > 0; off >>= 1) {
        v0 += __shfl_down_sync(m, v0, off);
        v1 += __shfl_down_sync(m, v1, off);
        v2 += __shfl_down_sync(m, v2, off);
        v3 += __shfl_down_sync(m, v3, off);
    }
    if (lane == 0) {
        red[0][wrp] = v0; red[1][wrp] = v1; red[2][wrp] = v2; red[3][wrp] = v3;
    }
    __syncthreads();

    if (wrp == 0) {
        float r0 = red[0][lane];
        float r1 = red[1][lane];
        float r2 = red[2][lane];
        float r3 = red[3][lane];
        #pragma unroll
        for (int off = 16; off > 0; off >>= 1) {
            r0 += __shfl_down_sync(m, r0, off);
            r1 += __shfl_down_sync(m, r1, off);
            r2 += __shfl_down_sync(m, r2, off);
            r3 += __shfl_down_sync(m, r3, off);
        }
        if (lane == 0) {
            const float b0 = __ldg(bd + 0);
            const float b1 = __ldg(bd + 1);
            const float hc00 = tanhf(r0 + b0);   // h_c[0,0]
            const float hc01 = tanhf(r1 + b1);   // h_c[0,1]
            const float hc10 = tanhf(r2 + b0);   // h_c[1,0]
            const float hc11 = tanhf(r3 + b1);   // h_c[1,1]
            const float den  = __ldg(f + 1) - __ldg(f + 2);
            out[0] = hc00;                       // h_out
            out[1] = hc01;
            out[2] = (hc00 - hc10) / den;        // H
            out[3] = (hc01 - hc11) / den;
        }
    }
}

// ---------------------------------------------------------------------------
extern "C" void kernel_launch(void* const* d_in, const int* in_sizes, int n_in,
                              void* d_out, int out_size) {
    (void)in_sizes; (void)n_in; (void)out_size;
    const float* x  = (const float*)d_in[0];   // inputs (1, 8192, 1024)
    const float* f  = (const float*)d_in[1];   // f (8192, 1)
    const float* W  = (const float*)d_in[2];   // (1024, 4096)
    const float* U  = (const float*)d_in[3];   // (1024, 4096)
    const float* b  = (const float*)d_in[4];   // (4096,)
    const float* Wd = (const float*)d_in[5];   // (1024, 2)
    const float* bd = (const float*)d_in[6];   // (2,)
    float* out = (float*)d_out;

    dim3 grid(NCB, KS);   // (4, 37) = 148 blocks = one per SM
    k_xw   <<<grid, 1024>>>(x, W);
    k_hu   <<<grid, 1024>>>(U, b);
    k_final<<<1, 1024>>>(f, b, Wd, bd, out);
}

// round 16
// speedup vs baseline: 1.9775x; 1.9775x over previous
#include <cuda_runtime.h>
#include <math.h>

#define UNITS 1024
#define FEAT  1024
#define GCOLS 4096                  // 4 * UNITS gate columns
#define CTILE 128                   // columns per block (32 lanes x float4)
#define NCB   (GCOLS / CTILE)       // 32 column tiles
#define KS    4                     // k-slices across blockIdx.y
#define KROWS (FEAT / KS)           // 256 k-rows per block
#define WARPS 32                    // warps per block (1024 threads)
#define KPW   (KROWS / WARPS)       // 8 k-rows per warp

// Scratch (device globals)
__device__ float4 g_p0[KS][GCOLS / 4];   // partials of x0@W (per k-slice)
__device__ float4 g_p1[KS][GCOLS / 4];   // partials of x1@W
__device__ float4 g_pu[KS][GCOLS / 4];   // partials of h0@U

__device__ __forceinline__ float sigmoidf_(float x) {
    return 1.0f / (1.0f + expf(-x));
}

// ---------------------------------------------------------------------------
// Kernel 1: partial GEMV over W for timesteps 0 and 1.
// grid = (NCB, KS) = (32, 4) = 128 blocks x 1024 threads.
// Block (cb, ks): columns [cb*128, cb*128+128), k in [ks*256, ks*256+256).
// Lane loads float4 of 4 consecutive columns -> 512B per warp load.
// Warp r covers k-rows r*8..r*8+7. 32-way fixed-order fold in shared.
// ---------------------------------------------------------------------------
__global__ void __launch_bounds__(1024, 1)
k_xw(const float* __restrict__ x, const float* __restrict__ W) {
    __shared__ float  xs0[KROWS], xs1[KROWS];
    __shared__ float4 sred0[WARPS][32];
    __shared__ float4 sred1[WARPS][32];
    const int tid  = threadIdx.x;
    const int lane = tid & 31;
    const int r    = tid >> 5;
    const int cb   = blockIdx.x;
    const int ks   = blockIdx.y;
    const int colv = cb * 32 + lane;          // float4-column index (0..1023)
    const int kbase = ks * KROWS;

    for (int i = tid; i < KROWS; i += 1024) {
        xs0[i] = x[kbase + i];
        xs1[i] = x[FEAT + kbase + i];
    }
    __syncthreads();

    const float4* Wp = reinterpret_cast<const float4*>(W)
                     + (size_t)(kbase + r * KPW) * (GCOLS / 4) + colv;
    float4 a0 = make_float4(0.f, 0.f, 0.f, 0.f);
    float4 a1 = make_float4(0.f, 0.f, 0.f, 0.f);
    #pragma unroll
    for (int kk = 0; kk < KPW; ++kk) {
        const float4 w = Wp[(size_t)kk * (GCOLS / 4)];
        const float xa = xs0[r * KPW + kk];
        const float xb = xs1[r * KPW + kk];
        a0.x = fmaf(xa, w.x, a0.x); a0.y = fmaf(xa, w.y, a0.y);
        a0.z = fmaf(xa, w.z, a0.z); a0.w = fmaf(xa, w.w, a0.w);
        a1.x = fmaf(xb, w.x, a1.x); a1.y = fmaf(xb, w.y, a1.y);
        a1.z = fmaf(xb, w.z, a1.z); a1.w = fmaf(xb, w.w, a1.w);
    }
    sred0[r][lane] = a0;
    sred1[r][lane] = a1;
    __syncthreads();

    if (tid < 32) {
        float4 s0 = make_float4(0.f, 0.f, 0.f, 0.f);
        #pragma unroll
        for (int rr = 0; rr < WARPS; ++rr) {
            const float4 v = sred0[rr][tid];
            s0.x += v.x; s0.y += v.y; s0.z += v.z; s0.w += v.w;
        }
        g_p0[ks][cb * 32 + tid] = s0;
    } else if (tid < 64) {
        const int c = tid - 32;
        float4 s1 = make_float4(0.f, 0.f, 0.f, 0.f);
        #pragma unroll
        for (int rr = 0; rr < WARPS; ++rr) {
            const float4 v = sred1[rr][c];
            s1.x += v.x; s1.y += v.y; s1.z += v.z; s1.w += v.w;
        }
        g_p1[ks][cb * 32 + c] = s1;
    }
}

// ---------------------------------------------------------------------------
// Helper: fold the KS partials of a gate column (fixed order) — scalar view.
// ---------------------------------------------------------------------------
__device__ __forceinline__ float fold_p(const float4 (*p)[GCOLS / 4], int col) {
    const float* base = reinterpret_cast<const float*>(p);
    float s = 0.f;
    #pragma unroll
    for (int sI = 0; sI < KS; ++sI) s += base[sI * GCOLS + col];
    return s;
}

// ---------------------------------------------------------------------------
// Kernel 2: partial GEMV over U. Same geometry as k_xw. Each block first
// reconstructs the 256 h0 values it needs from the x@W partials (+b):
// c0 = sig(zi)*zg, h0 = sig(zo)*c0  (c_prev = 0).
// ---------------------------------------------------------------------------
__global__ void __launch_bounds__(1024, 1)
k_hu(const float* __restrict__ U, const float* __restrict__ b) {
    __shared__ float  h0s[KROWS];
    __shared__ float4 sred[WARPS][32];
    const int tid  = threadIdx.x;
    const int lane = tid & 31;
    const int r    = tid >> 5;
    const int cb   = blockIdx.x;
    const int ks   = blockIdx.y;
    const int colv = cb * 32 + lane;
    const int kbase = ks * KROWS;

    if (tid < KROWS) {
        const int u = kbase + tid;
        const float zi = fold_p(g_p0, u)             + __ldg(b + u);
        const float zg = fold_p(g_p0, 2 * UNITS + u) + __ldg(b + 2 * UNITS + u);
        const float zo = fold_p(g_p0, 3 * UNITS + u) + __ldg(b + 3 * UNITS + u);
        const float c0 = sigmoidf_(zi) * zg;
        h0s[tid] = sigmoidf_(zo) * c0;
    }
    __syncthreads();

    const float4* Up = reinterpret_cast<const float4*>(U)
                     + (size_t)(kbase + r * KPW) * (GCOLS / 4) + colv;
    float4 a = make_float4(0.f, 0.f, 0.f, 0.f);
    #pragma unroll
    for (int kk = 0; kk < KPW; ++kk) {
        const float4 w = Up[(size_t)kk * (GCOLS / 4)];
        const float h = h0s[r * KPW + kk];
        a.x = fmaf(h, w.x, a.x); a.y = fmaf(h, w.y, a.y);
        a.z = fmaf(h, w.z, a.z); a.w = fmaf(h, w.w, a.w);
    }
    sred[r][lane] = a;
    __syncthreads();

    if (tid < 32) {
        float4 s = make_float4(0.f, 0.f, 0.f, 0.f);
        #pragma unroll
        for (int rr = 0; rr < WARPS; ++rr) {
            const float4 v = sred[rr][tid];
            s.x += v.x; s.y += v.y; s.z += v.z; s.w += v.w;
        }
        g_pu[ks][cb * 32 + tid] = s;
    }
}

// ---------------------------------------------------------------------------
// Kernel 3: one block, 1024 threads = UNITS. Fold all partials, gate math for
// t=0 and t=1, dense head via deterministic in-block reduction, finite diff.
// ---------------------------------------------------------------------------
__global__ void k_final(const float* __restrict__ f,
                        const float* __restrict__ b,
                        const float* __restrict__ Wd,
                        const float* __restrict__ bd,
                        float* __restrict__ out) {
    __shared__ float red[4][32];
    const int u = threadIdx.x;   // 0..1023

    // t=0 gates
    const float zi0 = fold_p(g_p0, u)             + __ldg(b + u);
    const float zg0 = fold_p(g_p0, 2 * UNITS + u) + __ldg(b + 2 * UNITS + u);
    const float zo0 = fold_p(g_p0, 3 * UNITS + u) + __ldg(b + 3 * UNITS + u);
    const float c0  = sigmoidf_(zi0) * zg0;
    const float h0  = sigmoidf_(zo0) * c0;

    // t=1 gates: z1 = x1@W + b + h0@U
    const float zi1 = fold_p(g_p1, u)             + fold_p(g_pu, u)             + __ldg(b + u);
    const float zf1 = fold_p(g_p1, UNITS + u)     + fold_p(g_pu, UNITS + u)     + __ldg(b + UNITS + u);
    const float zg1 = fold_p(g_p1, 2 * UNITS + u) + fold_p(g_pu, 2 * UNITS + u) + __ldg(b + 2 * UNITS + u);
    const float zo1 = fold_p(g_p1, 3 * UNITS + u) + fold_p(g_pu, 3 * UNITS + u) + __ldg(b + 3 * UNITS + u);
    const float c1  = sigmoidf_(zf1) * c0 + sigmoidf_(zi1) * zg1;
    const float h1  = sigmoidf_(zo1) * c1;

    const float n0 = tanhf(h0);
    const float n1 = tanhf(h1);

    const float wd0 = __ldg(Wd + 2 * u);
    const float wd1 = __ldg(Wd + 2 * u + 1);
    float v0 = n0 * wd0;   // -> h_c[0,0]
    float v1 = n0 * wd1;   // -> h_c[0,1]
    float v2 = n1 * wd0;   // -> h_c[1,0]
    float v3 = n1 * wd1;   // -> h_c[1,1]

    const unsigned m = 0xffffffffu;
    const int lane = u & 31;
    const int wrp  = u >> 5;
    #pragma unroll
    for (int off = 16; off > 0; off >>= 1) {
        v0 += __shfl_down_sync(m, v0, off);
        v1 += __shfl_down_sync(m, v1, off);
        v2 += __shfl_down_sync(m, v2, off);
        v3 += __shfl_down_sync(m, v3, off);
    }
    if (lane == 0) {
        red[0][wrp] = v0; red[1][wrp] = v1; red[2][wrp] = v2; red[3][wrp] = v3;
    }
    __syncthreads();

    if (wrp == 0) {
        float r0 = red[0][lane];
        float r1 = red[1][lane];
        float r2 = red[2][lane];
        float r3 = red[3][lane];
        #pragma unroll
        for (int off = 16; off > 0; off >>= 1) {
            r0 += __shfl_down_sync(m, r0, off);
            r1 += __shfl_down_sync(m, r1, off);
            r2 += __shfl_down_sync(m, r2, off);
            r3 += __shfl_down_sync(m, r3, off);
        }
        if (lane == 0) {
            const float b0 = __ldg(bd + 0);
            const float b1 = __ldg(bd + 1);
            const float hc00 = tanhf(r0 + b0);   // h_c[0,0]
            const float hc01 = tanhf(r1 + b1);   // h_c[0,1]
            const float hc10 = tanhf(r2 + b0);   // h_c[1,0]
            const float hc11 = tanhf(r3 + b1);   // h_c[1,1]
            const float den  = __ldg(f + 1) - __ldg(f + 2);
            out[0] = hc00;                       // h_out
            out[1] = hc01;
            out[2] = (hc00 - hc10) / den;        // H
            out[3] = (hc01 - hc11) / den;
        }
    }
}

// ---------------------------------------------------------------------------
extern "C" void kernel_launch(void* const* d_in, const int* in_sizes, int n_in,
                              void* d_out, int out_size) {
    (void)in_sizes; (void)n_in; (void)out_size;
    const float* x  = (const float*)d_in[0];   // inputs (1, 8192, 1024)
    const float* f  = (const float*)d_in[1];   // f (8192, 1)
    const float* W  = (const float*)d_in[2];   // (1024, 4096)
    const float* U  = (const float*)d_in[3];   // (1024, 4096)
    const float* b  = (const float*)d_in[4];   // (4096,)
    const float* Wd = (const float*)d_in[5];   // (1024, 2)
    const float* bd = (const float*)d_in[6];   // (2,)
    float* out = (float*)d_out;

    dim3 grid(NCB, KS);   // (32, 4) = 128 blocks
    k_xw   <<<grid, 1024>>>(x, W);
    k_hu   <<<grid, 1024>>>(U, b);
    k_final<<<1, 1024>>>(f, b, Wd, bd, out);
}